// round 7
// baseline (speedup 1.0000x reference)
#include <cuda_runtime.h>
#include <cuda_bf16.h>

// FilterLayer: y[b,c,h,w] = sum_{di,dj in 5x5} f[b, di*5+dj, h, w] * xpad[b, c, h+di, w+dj]
// x: [4,3,512,512] f32, f: [4,25,512,512] f32, out: [4,3,512,512] f32, zero pad p=2.
//
// R4: DRAM burst-length pass. 8 px/thread => each warp reads 1KB contiguous
// per filter plane per row (full HBM page) instead of 512B. Halves LDG
// instruction count per byte. No smem, no barrier.
//  - f via __ldcg (L2 path, zero reuse); x via default LDG (L1-resident, 25x reuse).
//  - taps for 8 px need cols [wb-2, wb+9] = 12 floats = 4 aligned float4
//    (v0 at wb-4 uses .z/.w, v1 at wb, v2 at wb+4, v3 at wb+8 uses .x/.y).

#define WIN 5
#define CH 3

__global__ __launch_bounds__(128, 5)
void FilterLayer_4664334483556_kernel(const float* __restrict__ x,
                                      const float* __restrict__ f,
                                      float* __restrict__ out)
{
    const int H = 512, W = 512;
    const int tx = threadIdx.x;                // 0..31
    const int ty = threadIdx.y;                // 0..3
    const int b  = blockIdx.z;
    const int h  = blockIdx.y * 4 + ty;        // output row
    const int wb = blockIdx.x * 256 + tx * 8;  // first of 8 output cols

    const bool leftOK  = (wb >= 4);            // v0 fully in-bounds
    const bool rightOK = (wb <= W - 12);       // v3 fully in-bounds

    float acc[CH][8];
    #pragma unroll
    for (int c = 0; c < CH; c++)
        #pragma unroll
        for (int q = 0; q < 8; q++)
            acc[c][q] = 0.0f;

    const size_t HW = (size_t)H * W;
    const float* fbase = f + ((size_t)b * (WIN * WIN)) * HW + (size_t)h * W + wb;
    const float* xbase = x + (size_t)b * CH * HW + wb;

    #pragma unroll
    for (int di = 0; di < WIN; di++) {
        const int gh = h + di - 2;
        const bool rv = ((unsigned)gh < (unsigned)H);

        // ---- filter row: 5 taps x 2 float4 = 10 LDG.128, 1KB/warp/plane ----
        float4 fa[WIN], fb[WIN];
        #pragma unroll
        for (int dj = 0; dj < WIN; dj++) {
            const float* fp = fbase + (size_t)(di * WIN + dj) * HW;
            fa[dj] = __ldcg(reinterpret_cast<const float4*>(fp));
            fb[dj] = __ldcg(reinterpret_cast<const float4*>(fp + 4));
        }

        #pragma unroll
        for (int c = 0; c < CH; c++) {
            const float* row = xbase + ((size_t)c * H + gh) * W;

            float4 v0 = make_float4(0.f, 0.f, 0.f, 0.f);
            float4 v1 = make_float4(0.f, 0.f, 0.f, 0.f);
            float4 v2 = make_float4(0.f, 0.f, 0.f, 0.f);
            float4 v3 = make_float4(0.f, 0.f, 0.f, 0.f);
            if (rv) {
                if (leftOK)  v0 = *reinterpret_cast<const float4*>(row - 4);
                             v1 = *reinterpret_cast<const float4*>(row);
                             v2 = *reinterpret_cast<const float4*>(row + 4);
                if (rightOK) v3 = *reinterpret_cast<const float4*>(row + 8);
            }

            // xr[i] = x[col wb-2+i], i in [0,12)
            float xr[12];
            xr[0]  = v0.z; xr[1]  = v0.w;
            xr[2]  = v1.x; xr[3]  = v1.y; xr[4]  = v1.z; xr[5]  = v1.w;
            xr[6]  = v2.x; xr[7]  = v2.y; xr[8]  = v2.z; xr[9]  = v2.w;
            xr[10] = v3.x; xr[11] = v3.y;

            #pragma unroll
            for (int dj = 0; dj < WIN; dj++) {
                acc[c][0] = fmaf(fa[dj].x, xr[dj + 0], acc[c][0]);
                acc[c][1] = fmaf(fa[dj].y, xr[dj + 1], acc[c][1]);
                acc[c][2] = fmaf(fa[dj].z, xr[dj + 2], acc[c][2]);
                acc[c][3] = fmaf(fa[dj].w, xr[dj + 3], acc[c][3]);
                acc[c][4] = fmaf(fb[dj].x, xr[dj + 4], acc[c][4]);
                acc[c][5] = fmaf(fb[dj].y, xr[dj + 5], acc[c][5]);
                acc[c][6] = fmaf(fb[dj].z, xr[dj + 6], acc[c][6]);
                acc[c][7] = fmaf(fb[dj].w, xr[dj + 7], acc[c][7]);
            }
        }
    }

    float* ob = out + (size_t)b * CH * HW + (size_t)h * W + wb;
    #pragma unroll
    for (int c = 0; c < CH; c++) {
        *reinterpret_cast<float4*>(ob + c * HW) =
            make_float4(acc[c][0], acc[c][1], acc[c][2], acc[c][3]);
        *reinterpret_cast<float4*>(ob + c * HW + 4) =
            make_float4(acc[c][4], acc[c][5], acc[c][6], acc[c][7]);
    }
}

extern "C" void kernel_launch(void* const* d_in, const int* in_sizes, int n_in,
                              void* d_out, int out_size)
{
    const float* x = (const float*)d_in[0];
    const float* f = (const float*)d_in[1];
    float* out = (float*)d_out;

    dim3 block(32, 4, 1);
    dim3 grid(2, 128, 4);   // (512/256, 512/4, B) = 1024 blocks
    FilterLayer_4664334483556_kernel<<<grid, block>>>(x, f, out);
}